// round 3
// baseline (speedup 1.0000x reference)
#include <cuda_runtime.h>
#include <cuda_bf16.h>
#include <cstdint>
#include <math.h>

#define B_DIM   16384
#define IN_DIM  784
#define H_DIM   4096
#define OUT_DIM 10
#define KPAD    832            // 784 padded to 13*64
#define NCHUNK  13             // K chunks of 64
#define MT      64
#define NT      128
#define STAGES  4

// smem stage layout: A limbs [3][64 rows][80B], B [128 rows][80B]
#define A_ROWB      80
#define A_LIMB_B    (64 * A_ROWB)          // 5120
#define STAGE_A_B   (3 * A_LIMB_B)         // 15360
#define STAGE_B_B   (128 * A_ROWB)         // 10240
#define STAGE_BYTES (STAGE_A_B + STAGE_B_B)  // 25600
#define SMEM_TOTAL  (STAGES * STAGE_BYTES)   // 102400

// ---------------- scratch ----------------
__device__ __align__(1024) int8_t g_Aq[(size_t)B_DIM * 3 * KPAD];   // 40.9 MB
__device__ __align__(1024) int8_t g_Bs[(size_t)H_DIM * KPAD];       // 3.4 MB
__device__ __align__(1024) float  g_h[(size_t)B_DIM * H_DIM];       // 268 MB
__device__ float    g_psum[128 * H_DIM];
__device__ float    g_psq [128 * H_DIM];
__device__ float    g_thr [H_DIM];
__device__ unsigned g_negw[H_DIM / 32];
__device__ unsigned g_w2b [OUT_DIM * (H_DIM / 32)];

// ---------------- helpers ----------------
__device__ __forceinline__ uint32_t smem_u32(const void* p) {
    uint32_t a;
    asm("{ .reg .u64 t; cvta.to.shared.u64 t, %1; cvt.u32.u64 %0, t; }" : "=r"(a) : "l"(p));
    return a;
}
__device__ __forceinline__ void cp_async16(uint32_t dst, const void* src) {
    asm volatile("cp.async.cg.shared.global [%0], [%1], 16;" :: "r"(dst), "l"(src) : "memory");
}
__device__ __forceinline__ void cp_commit() {
    asm volatile("cp.async.commit_group;" ::: "memory");
}
__device__ __forceinline__ void ldsm4(uint32_t addr, uint32_t* r) {
    asm volatile("ldmatrix.sync.aligned.m8n8.x4.shared.b16 {%0,%1,%2,%3}, [%4];"
                 : "=r"(r[0]), "=r"(r[1]), "=r"(r[2]), "=r"(r[3]) : "r"(addr));
}
__device__ __forceinline__ void ldsm2(uint32_t addr, uint32_t* r) {
    asm volatile("ldmatrix.sync.aligned.m8n8.x2.shared.b16 {%0,%1}, [%2];"
                 : "=r"(r[0]), "=r"(r[1]) : "r"(addr));
}
__device__ __forceinline__ void imma(int* d, const uint32_t* a, const uint32_t* b) {
    asm volatile(
        "mma.sync.aligned.m16n8k32.row.col.s32.s8.s8.s32 "
        "{%0,%1,%2,%3}, {%4,%5,%6,%7}, {%8,%9}, {%0,%1,%2,%3};"
        : "+r"(d[0]), "+r"(d[1]), "+r"(d[2]), "+r"(d[3])
        : "r"(a[0]), "r"(a[1]), "r"(a[2]), "r"(a[3]), "r"(b[0]), "r"(b[1]));
}

// ---------------- prep: x -> 3 int8 limbs at scale 2^-20 ----------------
__global__ void k_prep_a(const float* __restrict__ x) {
    size_t i = (size_t)blockIdx.x * blockDim.x + threadIdx.x;
    if (i >= (size_t)B_DIM * (KPAD / 4)) return;
    int row = (int)(i / (KPAD / 4));
    int k4  = (int)(i % (KPAD / 4));
    int k   = k4 * 4;
    char4 l0 = make_char4(0, 0, 0, 0), l1 = l0, l2 = l0;
    if (k < IN_DIM) {
        float4 xv = *(const float4*)(x + (size_t)row * IN_DIM + k);
        float v[4] = {xv.x, xv.y, xv.z, xv.w};
        signed char a0[4], a1[4], a2[4];
        #pragma unroll
        for (int j = 0; j < 4; j++) {
            int q = __float2int_rn(v[j] * 1048576.0f);
            q = max(min(q, 8388607), -8388607);
            int b0 = (q << 24) >> 24;
            int q1 = (q - b0) >> 8;
            int b1 = (q1 << 24) >> 24;
            int b2 = (q1 - b1) >> 8;
            a0[j] = (signed char)b0; a1[j] = (signed char)b1; a2[j] = (signed char)b2;
        }
        l0 = make_char4(a0[0], a0[1], a0[2], a0[3]);
        l1 = make_char4(a1[0], a1[1], a1[2], a1[3]);
        l2 = make_char4(a2[0], a2[1], a2[2], a2[3]);
    }
    size_t base = (size_t)row * 3 * KPAD + k;
    *(char4*)(g_Aq + base)            = l0;
    *(char4*)(g_Aq + base + KPAD)     = l1;
    *(char4*)(g_Aq + base + 2 * KPAD) = l2;
}

__global__ void k_prep_w(const float* __restrict__ W1) {
    size_t i = (size_t)blockIdx.x * blockDim.x + threadIdx.x;
    if (i >= (size_t)H_DIM * (KPAD / 4)) return;
    int row = (int)(i / (KPAD / 4));
    int k4  = (int)(i % (KPAD / 4));
    int k   = k4 * 4;
    char4 s = make_char4(0, 0, 0, 0);
    if (k < IN_DIM) {
        float4 wv = *(const float4*)(W1 + (size_t)row * IN_DIM + k);
        float v[4] = {wv.x, wv.y, wv.z, wv.w};
        signed char sc[4];
        #pragma unroll
        for (int j = 0; j < 4; j++)
            sc[j] = (signed char)((v[j] > 0.f) ? 1 : ((v[j] < 0.f) ? -1 : 0));
        s = make_char4(sc[0], sc[1], sc[2], sc[3]);
    }
    *(char4*)(g_Bs + (size_t)row * KPAD + k) = s;
}

__global__ void k_prep_w2(const float* __restrict__ W2) {
    int idx = blockIdx.x * blockDim.x + threadIdx.x;
    if (idx >= OUT_DIM * 128) return;
    int o = idx / 128, w = idx % 128;
    unsigned bits = 0;
    for (int j = 0; j < 32; j++)
        if (W2[(size_t)o * H_DIM + w * 32 + j] > 0.f) bits |= (1u << j);
    g_w2b[idx] = bits;
}

// ---------------- GEMM1 (int8 IMMA, 3 limb accumulators, shared B tile) ----------------
__global__ void __launch_bounds__(256) k_gemm1() {
    extern __shared__ __align__(128) char smem[];
    const uint32_t sb = smem_u32(smem);
    const int tid = threadIdx.x, lane = tid & 31, wid = tid >> 5;
    const int wm = wid & 1, wn = wid >> 1;
    const int mbase = blockIdx.y * MT;
    const int nbase = blockIdx.x * NT;

    // per-thread cp.async granule plan: 1280 granules/stage, 5 per thread
    const int8_t* gsrc[5];
    uint32_t sdst[5];
    #pragma unroll
    for (int i = 0; i < 5; i++) {
        int g = tid * 5 + i;
        if (g < 768) {
            int limb = g >> 8, rem = g & 255, row = rem >> 2, c = rem & 3;
            gsrc[i] = g_Aq + ((size_t)(mbase + row) * 3 + limb) * KPAD + c * 16;
            sdst[i] = limb * A_LIMB_B + row * A_ROWB + c * 16;
        } else {
            int gb = g - 768, row = gb >> 2, c = gb & 3;
            gsrc[i] = g_Bs + (size_t)(nbase + row) * KPAD + c * 16;
            sdst[i] = STAGE_A_B + row * A_ROWB + c * 16;
        }
    }

    // ldmatrix lane offsets
    const int mi = lane >> 3, r8 = lane & 7;
    const uint32_t aLane = ((mi & 1) * 8 + r8) * A_ROWB + (mi >> 1) * 16;
    const uint32_t bLane = (lane & 7) * A_ROWB + ((lane >> 3) & 1) * 16;

    int d[3][2][4][4];
    #pragma unroll
    for (int l = 0; l < 3; l++)
        #pragma unroll
        for (int mb = 0; mb < 2; mb++)
            #pragma unroll
            for (int nb = 0; nb < 4; nb++)
                #pragma unroll
                for (int i = 0; i < 4; i++) d[l][mb][nb][i] = 0;

    // prologue
    #pragma unroll
    for (int s = 0; s < STAGES - 1; s++) {
        #pragma unroll
        for (int i = 0; i < 5; i++)
            cp_async16(sb + s * STAGE_BYTES + sdst[i], gsrc[i] + s * 64);
        cp_commit();
    }

    for (int kc = 0; kc < NCHUNK; kc++) {
        if (kc < NCHUNK - 2)      asm volatile("cp.async.wait_group 2;" ::: "memory");
        else if (kc == NCHUNK - 2) asm volatile("cp.async.wait_group 1;" ::: "memory");
        else                       asm volatile("cp.async.wait_group 0;" ::: "memory");
        __syncthreads();

        if (kc + STAGES - 1 < NCHUNK) {
            int s = (kc + STAGES - 1) % STAGES;
            #pragma unroll
            for (int i = 0; i < 5; i++)
                cp_async16(sb + s * STAGE_BYTES + sdst[i], gsrc[i] + (kc + STAGES - 1) * 64);
            cp_commit();
        }

        const uint32_t sA = sb + (kc % STAGES) * STAGE_BYTES;
        const uint32_t sB = sA + STAGE_A_B;
        #pragma unroll
        for (int ks = 0; ks < 2; ks++) {
            uint32_t bfr[4][2];
            #pragma unroll
            for (int nb = 0; nb < 4; nb++)
                ldsm2(sB + (wn * 32 + nb * 8) * A_ROWB + ks * 32 + bLane, bfr[nb]);
            #pragma unroll
            for (int l = 0; l < 3; l++) {
                uint32_t afr[2][4];
                #pragma unroll
                for (int mb = 0; mb < 2; mb++)
                    ldsm4(sA + l * A_LIMB_B + (wm * 32 + mb * 16) * A_ROWB + ks * 32 + aLane, afr[mb]);
                #pragma unroll
                for (int mb = 0; mb < 2; mb++)
                    #pragma unroll
                    for (int nb = 0; nb < 4; nb++)
                        imma(d[l][mb][nb], afr[mb], bfr[nb]);
            }
        }
    }

    // epilogue: h = (65536*S2 + 256*S1 + S0) * 2^-20
    #pragma unroll
    for (int mb = 0; mb < 2; mb++) {
        int row0 = mbase + wm * 32 + mb * 16 + (lane >> 2);
        #pragma unroll
        for (int nb = 0; nb < 4; nb++) {
            int col = nbase + wn * 32 + nb * 8 + (lane & 3) * 2;
            float f[4];
            #pragma unroll
            for (int i = 0; i < 4; i++)
                f[i] = fmaf((float)d[2][mb][nb][i], 65536.f,
                            fmaf((float)d[1][mb][nb][i], 256.f,
                                 (float)d[0][mb][nb][i])) * (1.f / 1048576.f);
            *(float2*)(g_h + (size_t)row0 * H_DIM + col)       = make_float2(f[0], f[1]);
            *(float2*)(g_h + (size_t)(row0 + 8) * H_DIM + col) = make_float2(f[2], f[3]);
        }
    }
}

// ---------------- column stats (deterministic 2-stage) ----------------
__global__ void __launch_bounds__(256) k_stats_part() {
    int b = blockIdx.x, t = threadIdx.x;
    float s[16], q[16];
    #pragma unroll
    for (int c = 0; c < 16; c++) { s[c] = 0.f; q[c] = 0.f; }
    for (int r = 0; r < 128; r++) {
        const float* hp = g_h + (size_t)(b * 128 + r) * H_DIM + t;
        #pragma unroll
        for (int c = 0; c < 16; c++) { float v = hp[c * 256]; s[c] += v; q[c] += v * v; }
    }
    #pragma unroll
    for (int c = 0; c < 16; c++) {
        g_psum[(size_t)b * H_DIM + t + c * 256] = s[c];
        g_psq [(size_t)b * H_DIM + t + c * 256] = q[c];
    }
}

__global__ void __launch_bounds__(256) k_stats_fin(const float* __restrict__ gamma,
                                                   const float* __restrict__ beta) {
    int j = blockIdx.x * 256 + threadIdx.x;
    float s = 0.f, q = 0.f;
    for (int b = 0; b < 128; b++) {
        s += g_psum[(size_t)b * H_DIM + j];
        q += g_psq [(size_t)b * H_DIM + j];
    }
    float mean = s * (1.f / B_DIM);
    float var  = q * (1.f / B_DIM) - mean * mean;
    float a = gamma[j] * rsqrtf(var + 1e-5f);
    float t; unsigned neg;
    if (a != 0.f) { t = mean - beta[j] / a; neg = (a < 0.f) ? 1u : 0u; }
    else { t = (beta[j] > 0.f) ? -__int_as_float(0x7f800000) : __int_as_float(0x7f800000); neg = 0u; }
    g_thr[j] = t;
    unsigned word = __ballot_sync(0xFFFFFFFFu, neg);
    if ((threadIdx.x & 31) == 0) g_negw[j >> 5] = word;
}

// ---------------- fused sign / XOR-popcount GEMM2 / log-softmax ----------------
__global__ void __launch_bounds__(128) k_final(float* __restrict__ out) {
    int row = blockIdx.x;
    __shared__ unsigned hw[128];
    __shared__ int wsum[4][OUT_DIM];
    int tid = threadIdx.x, lane = tid & 31, w = tid >> 5;
    const float* hr = g_h + (size_t)row * H_DIM;
    for (int c = w; c < 128; c += 4) {
        int col = c * 32 + lane;
        unsigned bit = (hr[col] > g_thr[col]) ? 1u : 0u;
        unsigned word = __ballot_sync(0xFFFFFFFFu, bit);
        if (lane == 0) hw[c] = word ^ g_negw[c];
    }
    __syncthreads();
    unsigned mw = hw[tid];
    #pragma unroll
    for (int o = 0; o < OUT_DIM; o++) {
        int v = __popc(mw ^ g_w2b[o * 128 + tid]);
        v = (int)__reduce_add_sync(0xFFFFFFFFu, (unsigned)v);
        if (lane == 0) wsum[w][o] = v;
    }
    __syncthreads();
    if (tid == 0) {
        float lg[OUT_DIM], mx = -3.4e38f;
        #pragma unroll
        for (int o = 0; o < OUT_DIM; o++) {
            int mis = wsum[0][o] + wsum[1][o] + wsum[2][o] + wsum[3][o];
            lg[o] = (float)(H_DIM - 2 * mis);
            mx = fmaxf(mx, lg[o]);
        }
        float se = 0.f;
        #pragma unroll
        for (int o = 0; o < OUT_DIM; o++) se += expf(lg[o] - mx);
        float lse = mx + logf(se);
        #pragma unroll
        for (int o = 0; o < OUT_DIM; o++) out[(size_t)row * OUT_DIM + o] = lg[o] - lse;
    }
}

// ---------------- launch ----------------
extern "C" void kernel_launch(void* const* d_in, const int* in_sizes, int n_in,
                              void* d_out, int out_size) {
    (void)in_sizes; (void)n_in; (void)out_size;
    const float* x     = (const float*)d_in[0];
    const float* W1    = (const float*)d_in[1];
    const float* gamma = (const float*)d_in[2];
    const float* beta  = (const float*)d_in[3];
    const float* W2    = (const float*)d_in[4];

    cudaFuncSetAttribute(k_gemm1, cudaFuncAttributeMaxDynamicSharedMemorySize, SMEM_TOTAL);

    {
        size_t n = (size_t)B_DIM * (KPAD / 4);
        k_prep_a<<<(unsigned)((n + 255) / 256), 256>>>(x);
    }
    {
        size_t n = (size_t)H_DIM * (KPAD / 4);
        k_prep_w<<<(unsigned)((n + 255) / 256), 256>>>(W1);
    }
    k_prep_w2<<<10, 128>>>(W2);

    k_gemm1<<<dim3(H_DIM / NT, B_DIM / MT), 256, SMEM_TOTAL>>>();

    k_stats_part<<<128, 256>>>();
    k_stats_fin<<<H_DIM / 256, 256>>>(gamma, beta);

    k_final<<<B_DIM, 128>>>((float*)d_out);
}

// round 5
// speedup vs baseline: 1.0881x; 1.0881x over previous
#include <cuda_runtime.h>
#include <cstdint>
#include <math.h>

#define B_DIM   16384
#define IN_DIM  784
#define H_DIM   4096
#define OUT_DIM 10
#define KPAD    832            // 784 padded to 13*64
#define NCHUNK  13             // K chunks of 64
#define MT      64
#define NT      128
#define STAGES  4
#define MTILES  (B_DIM / MT)   // 256

// smem stage layout: A limbs [3][64 rows][80B], B [128 rows][80B]
#define A_ROWB      80
#define A_LIMB_B    (64 * A_ROWB)            // 5120
#define STAGE_A_B   (3 * A_LIMB_B)           // 15360
#define STAGE_B_B   (128 * A_ROWB)           // 10240
#define STAGE_BYTES (STAGE_A_B + STAGE_B_B)  // 25600
#define SMEM_TOTAL  (STAGES * STAGE_BYTES)   // 102400

// ---------------- scratch ----------------
__device__ __align__(1024) int8_t g_Aq[(size_t)B_DIM * 3 * KPAD];   // 40.9 MB
__device__ __align__(1024) int8_t g_Bs[(size_t)H_DIM * KPAD];       // 3.4 MB
__device__ __align__(1024) float  g_h[(size_t)B_DIM * H_DIM];       // 268 MB
__device__ float    g_psum[MTILES * H_DIM];
__device__ float    g_psq [MTILES * H_DIM];
__device__ float    g_thr [H_DIM];
__device__ unsigned g_negw[H_DIM / 32];
__device__ unsigned g_w2b [OUT_DIM * (H_DIM / 32)];

// ---------------- helpers ----------------
__device__ __forceinline__ uint32_t smem_u32(const void* p) {
    uint32_t a;
    asm("{ .reg .u64 t; cvta.to.shared.u64 t, %1; cvt.u32.u64 %0, t; }" : "=r"(a) : "l"(p));
    return a;
}
__device__ __forceinline__ void cp_async16(uint32_t dst, const void* src) {
    asm volatile("cp.async.cg.shared.global [%0], [%1], 16;" :: "r"(dst), "l"(src) : "memory");
}
__device__ __forceinline__ void cp_commit() {
    asm volatile("cp.async.commit_group;" ::: "memory");
}
__device__ __forceinline__ void ldsm4(uint32_t addr, uint32_t* r) {
    asm volatile("ldmatrix.sync.aligned.m8n8.x4.shared.b16 {%0,%1,%2,%3}, [%4];"
                 : "=r"(r[0]), "=r"(r[1]), "=r"(r[2]), "=r"(r[3]) : "r"(addr));
}
__device__ __forceinline__ void imma(int* d, const uint32_t* a, const uint32_t* b) {
    asm volatile(
        "mma.sync.aligned.m16n8k32.row.col.s32.s8.s8.s32 "
        "{%0,%1,%2,%3}, {%4,%5,%6,%7}, {%8,%9}, {%0,%1,%2,%3};"
        : "+r"(d[0]), "+r"(d[1]), "+r"(d[2]), "+r"(d[3])
        : "r"(a[0]), "r"(a[1]), "r"(a[2]), "r"(a[3]), "r"(b[0]), "r"(b[1]));
}

// ---------------- prep: x -> 3 int8 limbs at scale 2^-20 ----------------
__global__ void k_prep_a(const float* __restrict__ x) {
    size_t i = (size_t)blockIdx.x * blockDim.x + threadIdx.x;
    if (i >= (size_t)B_DIM * (KPAD / 4)) return;
    int row = (int)(i / (KPAD / 4));
    int k4  = (int)(i % (KPAD / 4));
    int k   = k4 * 4;
    char4 l0 = make_char4(0, 0, 0, 0), l1 = l0, l2 = l0;
    if (k < IN_DIM) {
        float4 xv = *(const float4*)(x + (size_t)row * IN_DIM + k);
        float v[4] = {xv.x, xv.y, xv.z, xv.w};
        signed char a0[4], a1[4], a2[4];
        #pragma unroll
        for (int j = 0; j < 4; j++) {
            int q = __float2int_rn(v[j] * 1048576.0f);
            q = max(min(q, 8388607), -8388607);
            int b0 = (q << 24) >> 24;
            int q1 = (q - b0) >> 8;
            int b1 = (q1 << 24) >> 24;
            int b2 = (q1 - b1) >> 8;
            a0[j] = (signed char)b0; a1[j] = (signed char)b1; a2[j] = (signed char)b2;
        }
        l0 = make_char4(a0[0], a0[1], a0[2], a0[3]);
        l1 = make_char4(a1[0], a1[1], a1[2], a1[3]);
        l2 = make_char4(a2[0], a2[1], a2[2], a2[3]);
    }
    size_t base = (size_t)row * 3 * KPAD + k;
    *(char4*)(g_Aq + base)            = l0;
    *(char4*)(g_Aq + base + KPAD)     = l1;
    *(char4*)(g_Aq + base + 2 * KPAD) = l2;
}

__global__ void k_prep_w(const float* __restrict__ W1) {
    size_t i = (size_t)blockIdx.x * blockDim.x + threadIdx.x;
    if (i >= (size_t)H_DIM * (KPAD / 4)) return;
    int row = (int)(i / (KPAD / 4));
    int k4  = (int)(i % (KPAD / 4));
    int k   = k4 * 4;
    char4 s = make_char4(0, 0, 0, 0);
    if (k < IN_DIM) {
        float4 wv = *(const float4*)(W1 + (size_t)row * IN_DIM + k);
        float v[4] = {wv.x, wv.y, wv.z, wv.w};
        signed char sc[4];
        #pragma unroll
        for (int j = 0; j < 4; j++)
            sc[j] = (signed char)((v[j] > 0.f) ? 1 : ((v[j] < 0.f) ? -1 : 0));
        s = make_char4(sc[0], sc[1], sc[2], sc[3]);
    }
    *(char4*)(g_Bs + (size_t)row * KPAD + k) = s;
}

__global__ void k_prep_w2(const float* __restrict__ W2) {
    int idx = blockIdx.x * blockDim.x + threadIdx.x;
    if (idx >= OUT_DIM * 128) return;
    int o = idx / 128, w = idx % 128;
    unsigned bits = 0;
    for (int j = 0; j < 32; j++)
        if (W2[(size_t)o * H_DIM + w * 32 + j] > 0.f) bits |= (1u << j);
    g_w2b[idx] = bits;
}

// ---------------- GEMM1 (int8 IMMA, 3 limb accumulators, fused stats) ----------------
__global__ void __launch_bounds__(256) k_gemm1() {
    extern __shared__ __align__(128) char smem[];
    const uint32_t sb = smem_u32(smem);
    const int tid = threadIdx.x, lane = tid & 31, wid = tid >> 5;
    const int wm = wid & 1, wn = wid >> 1;
    const int mbase = blockIdx.y * MT;
    const int nbase = blockIdx.x * NT;

    // per-thread cp.async granule plan: 1280 granules/stage, 5 per thread
    const int8_t* gsrc[5];
    uint32_t sdst[5];
    #pragma unroll
    for (int i = 0; i < 5; i++) {
        int g = tid * 5 + i;
        if (g < 768) {
            int limb = g >> 8, rem = g & 255, row = rem >> 2, c = rem & 3;
            gsrc[i] = g_Aq + ((size_t)(mbase + row) * 3 + limb) * KPAD + c * 16;
            sdst[i] = limb * A_LIMB_B + row * A_ROWB + c * 16;
        } else {
            int gb = g - 768, row = gb >> 2, c = gb & 3;
            gsrc[i] = g_Bs + (size_t)(nbase + row) * KPAD + c * 16;
            sdst[i] = STAGE_A_B + row * A_ROWB + c * 16;
        }
    }

    // ldmatrix lane offsets
    const int mi = lane >> 3, r8 = lane & 7;
    // A x4: rows (mi&1)*8+r8, col-half (mi>>1)*16   (per ks: +ks*32)
    const uint32_t aLane = (uint32_t)(((mi & 1) * 8 + r8) * A_ROWB + (mi >> 1) * 16);
    // B x4 covering BOTH ks: matrices {0,1}=ks0 halves, {2,3}=ks1 halves
    const uint32_t bLane = (uint32_t)(r8 * A_ROWB + (mi & 1) * 16 + (mi >> 1) * 32);

    int d[3][2][4][4];
    #pragma unroll
    for (int l = 0; l < 3; l++)
        #pragma unroll
        for (int mb = 0; mb < 2; mb++)
            #pragma unroll
            for (int nb = 0; nb < 4; nb++)
                #pragma unroll
                for (int i = 0; i < 4; i++) d[l][mb][nb][i] = 0;

    // prologue
    #pragma unroll
    for (int s = 0; s < STAGES - 1; s++) {
        #pragma unroll
        for (int i = 0; i < 5; i++)
            cp_async16(sb + s * STAGE_BYTES + sdst[i], gsrc[i] + s * 64);
        cp_commit();
    }

    for (int kc = 0; kc < NCHUNK; kc++) {
        if (kc < NCHUNK - 2)       asm volatile("cp.async.wait_group 2;" ::: "memory");
        else if (kc == NCHUNK - 2) asm volatile("cp.async.wait_group 1;" ::: "memory");
        else                       asm volatile("cp.async.wait_group 0;" ::: "memory");
        __syncthreads();

        if (kc + STAGES - 1 < NCHUNK) {
            int s = (kc + STAGES - 1) % STAGES;
            #pragma unroll
            for (int i = 0; i < 5; i++)
                cp_async16(sb + s * STAGE_BYTES + sdst[i], gsrc[i] + (kc + STAGES - 1) * 64);
            cp_commit();
        }

        const uint32_t sA = sb + (kc % STAGES) * STAGE_BYTES;
        const uint32_t sB = sA + STAGE_A_B;

        // ---- load ALL fragments for this chunk (both ks) up front ----
        uint32_t bfr[4][4];                 // [nb][ks0:{0,1}, ks1:{2,3}]
        #pragma unroll
        for (int nb = 0; nb < 4; nb++)
            ldsm4(sB + (uint32_t)((wn * 32 + nb * 8) * A_ROWB) + bLane, bfr[nb]);
        uint32_t afr[3][2][2][4];           // [limb][mb][ks][4]
        #pragma unroll
        for (int l = 0; l < 3; l++)
            #pragma unroll
            for (int mb = 0; mb < 2; mb++)
                #pragma unroll
                for (int ks = 0; ks < 2; ks++)
                    ldsm4(sA + l * A_LIMB_B + (uint32_t)((wm * 32 + mb * 16) * A_ROWB)
                             + (uint32_t)(ks * 32) + aLane, afr[l][mb][ks]);
        // ---- 48 independent MMAs ----
        #pragma unroll
        for (int ks = 0; ks < 2; ks++)
            #pragma unroll
            for (int l = 0; l < 3; l++)
                #pragma unroll
                for (int mb = 0; mb < 2; mb++)
                    #pragma unroll
                    for (int nb = 0; nb < 4; nb++)
                        imma(d[l][mb][nb], afr[l][mb][ks], &bfr[nb][ks * 2]);
    }

    // ---- epilogue: h = (65536*S2 + 256*S1 + S0) * 2^-20 + fused column stats ----
    float s_loc[4][2], q_loc[4][2];
    #pragma unroll
    for (int nb = 0; nb < 4; nb++) { s_loc[nb][0] = s_loc[nb][1] = 0.f; q_loc[nb][0] = q_loc[nb][1] = 0.f; }

    #pragma unroll
    for (int mb = 0; mb < 2; mb++) {
        int row0 = mbase + wm * 32 + mb * 16 + (lane >> 2);
        #pragma unroll
        for (int nb = 0; nb < 4; nb++) {
            int col = nbase + wn * 32 + nb * 8 + (lane & 3) * 2;
            float f[4];
            #pragma unroll
            for (int i = 0; i < 4; i++)
                f[i] = fmaf((float)d[2][mb][nb][i], 65536.f,
                            fmaf((float)d[1][mb][nb][i], 256.f,
                                 (float)d[0][mb][nb][i])) * (1.f / 1048576.f);
            *(float2*)(g_h + (size_t)row0 * H_DIM + col)       = make_float2(f[0], f[1]);
            *(float2*)(g_h + (size_t)(row0 + 8) * H_DIM + col) = make_float2(f[2], f[3]);
            s_loc[nb][0] += f[0] + f[2];            q_loc[nb][0] += f[0] * f[0] + f[2] * f[2];
            s_loc[nb][1] += f[1] + f[3];            q_loc[nb][1] += f[1] * f[1] + f[3] * f[3];
        }
    }
    // reduce across the 8 row-groups (lane>>2) within the warp
    #pragma unroll
    for (int nb = 0; nb < 4; nb++)
        #pragma unroll
        for (int p = 0; p < 2; p++) {
            #pragma unroll
            for (int off = 4; off <= 16; off <<= 1) {
                s_loc[nb][p] += __shfl_xor_sync(0xFFFFFFFFu, s_loc[nb][p], off);
                q_loc[nb][p] += __shfl_xor_sync(0xFFFFFFFFu, q_loc[nb][p], off);
            }
        }
    // combine wm halves through smem (fixed order -> deterministic)
    __syncthreads();
    float* sm_s = (float*)smem;         // 128 floats
    float* sm_q = sm_s + 128;           // 128 floats
    if (wm == 0 && lane < 4) {
        #pragma unroll
        for (int nb = 0; nb < 4; nb++)
            #pragma unroll
            for (int p = 0; p < 2; p++) {
                int idx = wn * 32 + nb * 8 + lane * 2 + p;
                sm_s[idx] = s_loc[nb][p];
                sm_q[idx] = q_loc[nb][p];
            }
    }
    __syncthreads();
    if (wm == 1 && lane < 4) {
        #pragma unroll
        for (int nb = 0; nb < 4; nb++)
            #pragma unroll
            for (int p = 0; p < 2; p++) {
                int idx = wn * 32 + nb * 8 + lane * 2 + p;
                size_t gidx = (size_t)blockIdx.y * H_DIM + nbase + idx;
                g_psum[gidx] = sm_s[idx] + s_loc[nb][p];
                g_psq [gidx] = sm_q[idx] + q_loc[nb][p];
            }
    }
}

// ---------------- stats finalize: reduce 256 mtile partials ----------------
__global__ void __launch_bounds__(256) k_stats_fin(const float* __restrict__ gamma,
                                                   const float* __restrict__ beta) {
    int j = blockIdx.x * 256 + threadIdx.x;
    float s = 0.f, q = 0.f;
    for (int p = 0; p < MTILES; p++) {
        s += g_psum[(size_t)p * H_DIM + j];
        q += g_psq [(size_t)p * H_DIM + j];
    }
    float mean = s * (1.f / B_DIM);
    float var  = q * (1.f / B_DIM) - mean * mean;
    float a = gamma[j] * rsqrtf(var + 1e-5f);
    float t; unsigned neg;
    if (a != 0.f) { t = mean - beta[j] / a; neg = (a < 0.f) ? 1u : 0u; }
    else { t = (beta[j] > 0.f) ? -__int_as_float(0x7f800000) : __int_as_float(0x7f800000); neg = 0u; }
    g_thr[j] = t;
    unsigned word = __ballot_sync(0xFFFFFFFFu, neg);
    if ((threadIdx.x & 31) == 0) g_negw[j >> 5] = word;
}

// ---------------- fused sign / XOR-popcount GEMM2 / log-softmax ----------------
__global__ void __launch_bounds__(128) k_final(float* __restrict__ out) {
    int row = blockIdx.x;
    __shared__ unsigned hw[128];
    __shared__ int wsum[4][OUT_DIM];
    int tid = threadIdx.x, lane = tid & 31, w = tid >> 5;
    const float* hr = g_h + (size_t)row * H_DIM;
    for (int c = w; c < 128; c += 4) {
        int col = c * 32 + lane;
        unsigned bit = (hr[col] > g_thr[col]) ? 1u : 0u;
        unsigned word = __ballot_sync(0xFFFFFFFFu, bit);
        if (lane == 0) hw[c] = word ^ g_negw[c];
    }
    __syncthreads();
    unsigned mw = hw[tid];
    #pragma unroll
    for (int o = 0; o < OUT_DIM; o++) {
        int v = __popc(mw ^ g_w2b[o * 128 + tid]);
        v = (int)__reduce_add_sync(0xFFFFFFFFu, (unsigned)v);
        if (lane == 0) wsum[w][o] = v;
    }
    __syncthreads();
    if (tid == 0) {
        float lg[OUT_DIM], mx = -3.4e38f;
        #pragma unroll
        for (int o = 0; o < OUT_DIM; o++) {
            int mis = wsum[0][o] + wsum[1][o] + wsum[2][o] + wsum[3][o];
            lg[o] = (float)(H_DIM - 2 * mis);
            mx = fmaxf(mx, lg[o]);
        }
        float se = 0.f;
        #pragma unroll
        for (int o = 0; o < OUT_DIM; o++) se += expf(lg[o] - mx);
        float lse = mx + logf(se);
        #pragma unroll
        for (int o = 0; o < OUT_DIM; o++) out[(size_t)row * OUT_DIM + o] = lg[o] - lse;
    }
}

// ---------------- launch ----------------
extern "C" void kernel_launch(void* const* d_in, const int* in_sizes, int n_in,
                              void* d_out, int out_size) {
    (void)in_sizes; (void)n_in; (void)out_size;
    const float* x     = (const float*)d_in[0];
    const float* W1    = (const float*)d_in[1];
    const float* gamma = (const float*)d_in[2];
    const float* beta  = (const float*)d_in[3];
    const float* W2    = (const float*)d_in[4];

    cudaFuncSetAttribute(k_gemm1, cudaFuncAttributeMaxDynamicSharedMemorySize, SMEM_TOTAL);

    {
        size_t n = (size_t)B_DIM * (KPAD / 4);
        k_prep_a<<<(unsigned)((n + 255) / 256), 256>>>(x);
    }
    {
        size_t n = (size_t)H_DIM * (KPAD / 4);
        k_prep_w<<<(unsigned)((n + 255) / 256), 256>>>(W1);
    }
    k_prep_w2<<<10, 128>>>(W2);

    k_gemm1<<<dim3(H_DIM / NT, B_DIM / MT), 256, SMEM_TOTAL>>>();

    k_stats_fin<<<H_DIM / 256, 256>>>(gamma, beta);

    k_final<<<B_DIM, 128>>>((float*)d_out);
}

// round 7
// speedup vs baseline: 1.3664x; 1.2558x over previous
#include <cuda_runtime.h>
#include <cstdint>
#include <math.h>

#define B_DIM   16384
#define IN_DIM  784
#define H_DIM   4096
#define OUT_DIM 10
#define KPAD    832            // 784 padded to 13*64
#define NCHUNK  13             // K chunks of 64
#define MT      64
#define NT      128
#define STAGES  4
#define MTILES  (B_DIM / MT)   // 256

// smem stage layout: A limbs [3][64 rows][80B], B [128 rows][80B]
#define A_ROWB      80
#define A_LIMB_B    (64 * A_ROWB)            // 5120
#define STAGE_A_B   (3 * A_LIMB_B)           // 15360
#define STAGE_B_B   (128 * A_ROWB)           // 10240
#define STAGE_BYTES (STAGE_A_B + STAGE_B_B)  // 25600
#define SMEM_TOTAL  (STAGES * STAGE_BYTES)   // 102400

// ---------------- scratch ----------------
__device__ __align__(1024) int8_t g_Aq[(size_t)B_DIM * 3 * KPAD];   // 40.9 MB
__device__ __align__(1024) int8_t g_Bs[(size_t)H_DIM * KPAD];       // 3.4 MB
__device__ __align__(1024) float  g_h[(size_t)B_DIM * H_DIM];       // 268 MB
__device__ float    g_psum[MTILES * H_DIM];
__device__ float    g_psq [MTILES * H_DIM];
__device__ float    g_thr [H_DIM];
__device__ unsigned g_negw[H_DIM / 32];
__device__ unsigned g_w2b [OUT_DIM * (H_DIM / 32)];

// ---------------- helpers ----------------
__device__ __forceinline__ uint32_t smem_u32(const void* p) {
    uint32_t a;
    asm("{ .reg .u64 t; cvta.to.shared.u64 t, %1; cvt.u32.u64 %0, t; }" : "=r"(a) : "l"(p));
    return a;
}
__device__ __forceinline__ void cp_async16(uint32_t dst, const void* src) {
    asm volatile("cp.async.cg.shared.global [%0], [%1], 16;" :: "r"(dst), "l"(src) : "memory");
}
__device__ __forceinline__ void cp_commit() {
    asm volatile("cp.async.commit_group;" ::: "memory");
}
__device__ __forceinline__ void ldsm4(uint32_t addr, uint32_t* r) {
    asm volatile("ldmatrix.sync.aligned.m8n8.x4.shared.b16 {%0,%1,%2,%3}, [%4];"
                 : "=r"(r[0]), "=r"(r[1]), "=r"(r[2]), "=r"(r[3]) : "r"(addr));
}
__device__ __forceinline__ void imma(int* d, const uint32_t* a, const uint32_t* b) {
    asm volatile(
        "mma.sync.aligned.m16n8k32.row.col.s32.s8.s8.s32 "
        "{%0,%1,%2,%3}, {%4,%5,%6,%7}, {%8,%9}, {%0,%1,%2,%3};"
        : "+r"(d[0]), "+r"(d[1]), "+r"(d[2]), "+r"(d[3])
        : "r"(a[0]), "r"(a[1]), "r"(a[2]), "r"(a[3]), "r"(b[0]), "r"(b[1]));
}

// ---------------- prep: x -> 3 int8 limbs at scale 2^-20 ----------------
__global__ void k_prep_a(const float* __restrict__ x) {
    size_t i = (size_t)blockIdx.x * blockDim.x + threadIdx.x;
    if (i >= (size_t)B_DIM * (KPAD / 4)) return;
    int row = (int)(i / (KPAD / 4));
    int k4  = (int)(i % (KPAD / 4));
    int k   = k4 * 4;
    char4 l0 = make_char4(0, 0, 0, 0), l1 = l0, l2 = l0;
    if (k < IN_DIM) {
        float4 xv = *(const float4*)(x + (size_t)row * IN_DIM + k);
        float v[4] = {xv.x, xv.y, xv.z, xv.w};
        signed char a0[4], a1[4], a2[4];
        #pragma unroll
        for (int j = 0; j < 4; j++) {
            int q = __float2int_rn(v[j] * 1048576.0f);
            q = max(min(q, 8388607), -8388607);
            int b0 = (q << 24) >> 24;
            int q1 = (q - b0) >> 8;
            int b1 = (q1 << 24) >> 24;
            int b2 = (q1 - b1) >> 8;
            a0[j] = (signed char)b0; a1[j] = (signed char)b1; a2[j] = (signed char)b2;
        }
        l0 = make_char4(a0[0], a0[1], a0[2], a0[3]);
        l1 = make_char4(a1[0], a1[1], a1[2], a1[3]);
        l2 = make_char4(a2[0], a2[1], a2[2], a2[3]);
    }
    size_t base = (size_t)row * 3 * KPAD + k;
    *(char4*)(g_Aq + base)            = l0;
    *(char4*)(g_Aq + base + KPAD)     = l1;
    *(char4*)(g_Aq + base + 2 * KPAD) = l2;
}

__global__ void k_prep_w(const float* __restrict__ W1) {
    size_t i = (size_t)blockIdx.x * blockDim.x + threadIdx.x;
    if (i >= (size_t)H_DIM * (KPAD / 4)) return;
    int row = (int)(i / (KPAD / 4));
    int k4  = (int)(i % (KPAD / 4));
    int k   = k4 * 4;
    char4 s = make_char4(0, 0, 0, 0);
    if (k < IN_DIM) {
        float4 wv = *(const float4*)(W1 + (size_t)row * IN_DIM + k);
        float v[4] = {wv.x, wv.y, wv.z, wv.w};
        signed char sc[4];
        #pragma unroll
        for (int j = 0; j < 4; j++)
            sc[j] = (signed char)((v[j] > 0.f) ? 1 : ((v[j] < 0.f) ? -1 : 0));
        s = make_char4(sc[0], sc[1], sc[2], sc[3]);
    }
    *(char4*)(g_Bs + (size_t)row * KPAD + k) = s;
}

__global__ void k_prep_w2(const float* __restrict__ W2) {
    int idx = blockIdx.x * blockDim.x + threadIdx.x;
    if (idx >= OUT_DIM * 128) return;
    int o = idx / 128, w = idx % 128;
    unsigned bits = 0;
    for (int j = 0; j < 32; j++)
        if (W2[(size_t)o * H_DIM + w * 32 + j] > 0.f) bits |= (1u << j);
    g_w2b[idx] = bits;
}

// ---------------- GEMM1: 512 threads, warp tile M16xN32, fused stats ----------------
__global__ void __launch_bounds__(512, 1) k_gemm1() {
    extern __shared__ __align__(128) char smem[];
    const uint32_t sb = smem_u32(smem);
    const int tid = threadIdx.x, lane = tid & 31, wid = tid >> 5;
    const int wm = wid & 3, wn = wid >> 2;       // 4 x 4 warp grid
    const int mbase = blockIdx.y * MT;
    const int nbase = blockIdx.x * NT;

    // cp.async granule plan: 1280 granules/stage; threads get granules tid, tid+512, (tid<256: tid+1024)
    const int ng = (tid < 256) ? 3 : 2;
    const int8_t* gsrc[3];
    uint32_t sdst[3];
    #pragma unroll
    for (int i = 0; i < 3; i++) {
        int g = tid + i * 512;
        if (g >= 1280) g = 0;   // dummy (unused when i >= ng)
        if (g < 768) {
            int limb = g >> 8, rem = g & 255, row = rem >> 2, c = rem & 3;
            gsrc[i] = g_Aq + ((size_t)(mbase + row) * 3 + limb) * KPAD + c * 16;
            sdst[i] = limb * A_LIMB_B + row * A_ROWB + c * 16;
        } else {
            int gb = g - 768, row = gb >> 2, c = gb & 3;
            gsrc[i] = g_Bs + (size_t)(nbase + row) * KPAD + c * 16;
            sdst[i] = STAGE_A_B + row * A_ROWB + c * 16;
        }
    }

    // ldmatrix lane offsets
    const int mi = lane >> 3, r8 = lane & 7;
    // A x4: 16 rows x 32 bytes: rows (mi&1)*8+r8, col-half (mi>>1)*16   (+ks*32)
    const uint32_t aLane = (uint32_t)(((mi & 1) * 8 + r8) * A_ROWB + (mi >> 1) * 16);
    // B x4 covering BOTH ks: {ks0lo, ks0hi, ks1lo, ks1hi} for one 8-row group
    const uint32_t bLane = (uint32_t)(r8 * A_ROWB + (mi & 1) * 16 + (mi >> 1) * 32);

    int d[3][4][4];
    #pragma unroll
    for (int l = 0; l < 3; l++)
        #pragma unroll
        for (int nb = 0; nb < 4; nb++)
            #pragma unroll
            for (int i = 0; i < 4; i++) d[l][nb][i] = 0;

    // prologue
    #pragma unroll
    for (int s = 0; s < STAGES - 1; s++) {
        #pragma unroll
        for (int i = 0; i < 3; i++)
            if (i < ng) cp_async16(sb + s * STAGE_BYTES + sdst[i], gsrc[i] + s * 64);
        cp_commit();
    }

    const uint32_t aWarp = (uint32_t)(wm * 16 * A_ROWB) + aLane;
    const uint32_t bWarp = (uint32_t)(wn * 32 * A_ROWB) + bLane;

    for (int kc = 0; kc < NCHUNK; kc++) {
        if (kc < NCHUNK - 2)       asm volatile("cp.async.wait_group 2;" ::: "memory");
        else if (kc == NCHUNK - 2) asm volatile("cp.async.wait_group 1;" ::: "memory");
        else                       asm volatile("cp.async.wait_group 0;" ::: "memory");
        __syncthreads();

        if (kc + STAGES - 1 < NCHUNK) {
            int s = (kc + STAGES - 1) % STAGES;
            #pragma unroll
            for (int i = 0; i < 3; i++)
                if (i < ng) cp_async16(sb + s * STAGE_BYTES + sdst[i], gsrc[i] + (kc + STAGES - 1) * 64);
            cp_commit();
        }

        const uint32_t sA = sb + (kc % STAGES) * STAGE_BYTES;
        const uint32_t sB = sA + STAGE_A_B;

        uint32_t bfr[4][4];
        #pragma unroll
        for (int nb = 0; nb < 4; nb++)
            ldsm4(sB + bWarp + (uint32_t)(nb * 8 * A_ROWB), bfr[nb]);
        uint32_t afr[3][2][4];
        #pragma unroll
        for (int l = 0; l < 3; l++)
            #pragma unroll
            for (int ks = 0; ks < 2; ks++)
                ldsm4(sA + l * A_LIMB_B + aWarp + (uint32_t)(ks * 32), afr[l][ks]);

        // 24 independent MMAs
        #pragma unroll
        for (int ks = 0; ks < 2; ks++)
            #pragma unroll
            for (int l = 0; l < 3; l++)
                #pragma unroll
                for (int nb = 0; nb < 4; nb++)
                    imma(d[l][nb], afr[l][ks], &bfr[nb][ks * 2]);
    }

    // ---- epilogue: h = (65536*S2 + 256*S1 + S0) * 2^-20 + fused column stats ----
    float s_loc[4][2], q_loc[4][2];
    #pragma unroll
    for (int nb = 0; nb < 4; nb++) { s_loc[nb][0] = s_loc[nb][1] = 0.f; q_loc[nb][0] = q_loc[nb][1] = 0.f; }

    {
        int row0 = mbase + wm * 16 + (lane >> 2);
        #pragma unroll
        for (int nb = 0; nb < 4; nb++) {
            int col = nbase + wn * 32 + nb * 8 + (lane & 3) * 2;
            float f[4];
            #pragma unroll
            for (int i = 0; i < 4; i++)
                f[i] = fmaf((float)d[2][nb][i], 65536.f,
                            fmaf((float)d[1][nb][i], 256.f,
                                 (float)d[0][nb][i])) * (1.f / 1048576.f);
            *(float2*)(g_h + (size_t)row0 * H_DIM + col)       = make_float2(f[0], f[1]);
            *(float2*)(g_h + (size_t)(row0 + 8) * H_DIM + col) = make_float2(f[2], f[3]);
            s_loc[nb][0] += f[0] + f[2];            q_loc[nb][0] += f[0] * f[0] + f[2] * f[2];
            s_loc[nb][1] += f[1] + f[3];            q_loc[nb][1] += f[1] * f[1] + f[3] * f[3];
        }
    }
    // reduce across the 8 row-groups within the warp
    #pragma unroll
    for (int nb = 0; nb < 4; nb++)
        #pragma unroll
        for (int p = 0; p < 2; p++) {
            #pragma unroll
            for (int off = 4; off <= 16; off <<= 1) {
                s_loc[nb][p] += __shfl_xor_sync(0xFFFFFFFFu, s_loc[nb][p], off);
                q_loc[nb][p] += __shfl_xor_sync(0xFFFFFFFFu, q_loc[nb][p], off);
            }
        }
    // combine 4 wm groups through smem (fixed order -> deterministic)
    __syncthreads();
    float* sm_s = (float*)smem;          // [4][128]
    float* sm_q = sm_s + 512;            // [4][128]
    if (lane < 4) {
        #pragma unroll
        for (int nb = 0; nb < 4; nb++)
            #pragma unroll
            for (int p = 0; p < 2; p++) {
                int idx = wn * 32 + nb * 8 + lane * 2 + p;
                sm_s[wm * 128 + idx] = s_loc[nb][p];
                sm_q[wm * 128 + idx] = q_loc[nb][p];
            }
    }
    __syncthreads();
    if (tid < 128) {
        float s = ((sm_s[tid] + sm_s[128 + tid]) + sm_s[256 + tid]) + sm_s[384 + tid];
        float q = ((sm_q[tid] + sm_q[128 + tid]) + sm_q[256 + tid]) + sm_q[384 + tid];
        size_t gidx = (size_t)blockIdx.y * H_DIM + nbase + tid;
        g_psum[gidx] = s;
        g_psq [gidx] = q;
    }
}

// ---------------- stats finalize: reduce 256 mtile partials ----------------
__global__ void __launch_bounds__(256) k_stats_fin(const float* __restrict__ gamma,
                                                   const float* __restrict__ beta) {
    int j = blockIdx.x * 256 + threadIdx.x;
    float s = 0.f, q = 0.f;
    for (int p = 0; p < MTILES; p++) {
        s += g_psum[(size_t)p * H_DIM + j];
        q += g_psq [(size_t)p * H_DIM + j];
    }
    float mean = s * (1.f / B_DIM);
    float var  = q * (1.f / B_DIM) - mean * mean;
    float a = gamma[j] * rsqrtf(var + 1e-5f);
    float t; unsigned neg;
    if (a != 0.f) { t = mean - beta[j] / a; neg = (a < 0.f) ? 1u : 0u; }
    else { t = (beta[j] > 0.f) ? -__int_as_float(0x7f800000) : __int_as_float(0x7f800000); neg = 0u; }
    g_thr[j] = t;
    unsigned word = __ballot_sync(0xFFFFFFFFu, neg);
    if ((threadIdx.x & 31) == 0) g_negw[j >> 5] = word;
}

// ---------------- fused sign / XOR-popcount GEMM2 / log-softmax ----------------
__global__ void __launch_bounds__(128) k_final(float* __restrict__ out) {
    int row = blockIdx.x;
    __shared__ unsigned hw[128];
    __shared__ int wsum[4][OUT_DIM];
    int tid = threadIdx.x, lane = tid & 31, w = tid >> 5;
    const float* hr = g_h + (size_t)row * H_DIM;
    for (int c = w; c < 128; c += 4) {
        int col = c * 32 + lane;
        unsigned bit = (hr[col] > g_thr[col]) ? 1u : 0u;
        unsigned word = __ballot_sync(0xFFFFFFFFu, bit);
        if (lane == 0) hw[c] = word ^ g_negw[c];
    }
    __syncthreads();
    unsigned mw = hw[tid];
    #pragma unroll
    for (int o = 0; o < OUT_DIM; o++) {
        int v = __popc(mw ^ g_w2b[o * 128 + tid]);
        v = (int)__reduce_add_sync(0xFFFFFFFFu, (unsigned)v);
        if (lane == 0) wsum[w][o] = v;
    }
    __syncthreads();
    if (tid == 0) {
        float lg[OUT_DIM], mx = -3.4e38f;
        #pragma unroll
        for (int o = 0; o < OUT_DIM; o++) {
            int mis = wsum[0][o] + wsum[1][o] + wsum[2][o] + wsum[3][o];
            lg[o] = (float)(H_DIM - 2 * mis);
            mx = fmaxf(mx, lg[o]);
        }
        float se = 0.f;
        #pragma unroll
        for (int o = 0; o < OUT_DIM; o++) se += expf(lg[o] - mx);
        float lse = mx + logf(se);
        #pragma unroll
        for (int o = 0; o < OUT_DIM; o++) out[(size_t)row * OUT_DIM + o] = lg[o] - lse;
    }
}

// ---------------- launch ----------------
extern "C" void kernel_launch(void* const* d_in, const int* in_sizes, int n_in,
                              void* d_out, int out_size) {
    (void)in_sizes; (void)n_in; (void)out_size;
    const float* x     = (const float*)d_in[0];
    const float* W1    = (const float*)d_in[1];
    const float* gamma = (const float*)d_in[2];
    const float* beta  = (const float*)d_in[3];
    const float* W2    = (const float*)d_in[4];

    cudaFuncSetAttribute(k_gemm1, cudaFuncAttributeMaxDynamicSharedMemorySize, SMEM_TOTAL);

    {
        size_t n = (size_t)B_DIM * (KPAD / 4);
        k_prep_a<<<(unsigned)((n + 255) / 256), 256>>>(x);
    }
    {
        size_t n = (size_t)H_DIM * (KPAD / 4);
        k_prep_w<<<(unsigned)((n + 255) / 256), 256>>>(W1);
    }
    k_prep_w2<<<10, 128>>>(W2);

    k_gemm1<<<dim3(H_DIM / NT, B_DIM / MT), 512, SMEM_TOTAL>>>();

    k_stats_fin<<<H_DIM / 256, 256>>>(gamma, beta);

    k_final<<<B_DIM, 128>>>((float*)d_out);
}

// round 8
// speedup vs baseline: 1.6474x; 1.2056x over previous
#include <cuda_runtime.h>
#include <cstdint>
#include <math.h>

#define B_DIM   16384
#define IN_DIM  784
#define H_DIM   4096
#define OUT_DIM 10
#define KPAD    832            // 784 padded to 13*64
#define NCHUNK  13             // K chunks of 64
#define MT      64
#define NT      128
#define STAGES  4
#define MTILES  (B_DIM / MT)   // 256

// smem stage layout: A limbs [3][64 rows][80B], B [128 rows][80B]
#define A_ROWB      80
#define A_LIMB_B    (64 * A_ROWB)            // 5120
#define STAGE_A_B   (3 * A_LIMB_B)           // 15360
#define STAGE_B_B   (128 * A_ROWB)           // 10240
#define STAGE_BYTES (STAGE_A_B + STAGE_B_B)  // 25600
#define SMEM_TOTAL  (STAGES * STAGE_BYTES)   // 102400

// ---------------- scratch ----------------
__device__ __align__(1024) int8_t g_Aq[(size_t)B_DIM * 3 * KPAD];   // 40.9 MB
__device__ __align__(1024) int8_t g_Bs[(size_t)H_DIM * KPAD];       // 3.4 MB
__device__ __align__(1024) float  g_h[(size_t)B_DIM * H_DIM];       // 268 MB
__device__ float    g_psum[MTILES * H_DIM];
__device__ float    g_psq [MTILES * H_DIM];
__device__ float    g_thr [H_DIM];
__device__ unsigned g_negw[H_DIM / 32];
__device__ unsigned g_w2b [OUT_DIM * (H_DIM / 32)];

// ---------------- helpers ----------------
__device__ __forceinline__ uint32_t smem_u32(const void* p) {
    uint32_t a;
    asm("{ .reg .u64 t; cvta.to.shared.u64 t, %1; cvt.u32.u64 %0, t; }" : "=r"(a) : "l"(p));
    return a;
}
__device__ __forceinline__ void cp_async16(uint32_t dst, const void* src) {
    asm volatile("cp.async.cg.shared.global [%0], [%1], 16;" :: "r"(dst), "l"(src) : "memory");
}
__device__ __forceinline__ void cp_commit() {
    asm volatile("cp.async.commit_group;" ::: "memory");
}
__device__ __forceinline__ void ldsm4(uint32_t addr, uint32_t* r) {
    asm volatile("ldmatrix.sync.aligned.m8n8.x4.shared.b16 {%0,%1,%2,%3}, [%4];"
                 : "=r"(r[0]), "=r"(r[1]), "=r"(r[2]), "=r"(r[3]) : "r"(addr));
}
__device__ __forceinline__ void imma(int* d, const uint32_t* a, const uint32_t* b) {
    asm volatile(
        "mma.sync.aligned.m16n8k32.row.col.s32.s8.s8.s32 "
        "{%0,%1,%2,%3}, {%4,%5,%6,%7}, {%8,%9}, {%0,%1,%2,%3};"
        : "+r"(d[0]), "+r"(d[1]), "+r"(d[2]), "+r"(d[3])
        : "r"(a[0]), "r"(a[1]), "r"(a[2]), "r"(a[3]), "r"(b[0]), "r"(b[1]));
}

// ---------------- prep: x -> 3 int8 limbs at scale 2^-20 ----------------
__global__ void k_prep_a(const float* __restrict__ x) {
    size_t i = (size_t)blockIdx.x * blockDim.x + threadIdx.x;
    if (i >= (size_t)B_DIM * (KPAD / 4)) return;
    int row = (int)(i / (KPAD / 4));
    int k4  = (int)(i % (KPAD / 4));
    int k   = k4 * 4;
    char4 l0 = make_char4(0, 0, 0, 0), l1 = l0, l2 = l0;
    if (k < IN_DIM) {
        float4 xv = *(const float4*)(x + (size_t)row * IN_DIM + k);
        float v[4] = {xv.x, xv.y, xv.z, xv.w};
        signed char a0[4], a1[4], a2[4];
        #pragma unroll
        for (int j = 0; j < 4; j++) {
            int q = __float2int_rn(v[j] * 1048576.0f);
            q = max(min(q, 8388607), -8388607);
            int b0 = (q << 24) >> 24;
            int q1 = (q - b0) >> 8;
            int b1 = (q1 << 24) >> 24;
            int b2 = (q1 - b1) >> 8;
            a0[j] = (signed char)b0; a1[j] = (signed char)b1; a2[j] = (signed char)b2;
        }
        l0 = make_char4(a0[0], a0[1], a0[2], a0[3]);
        l1 = make_char4(a1[0], a1[1], a1[2], a1[3]);
        l2 = make_char4(a2[0], a2[1], a2[2], a2[3]);
    }
    size_t base = (size_t)row * 3 * KPAD + k;
    *(char4*)(g_Aq + base)            = l0;
    *(char4*)(g_Aq + base + KPAD)     = l1;
    *(char4*)(g_Aq + base + 2 * KPAD) = l2;
}

__global__ void k_prep_w(const float* __restrict__ W1) {
    size_t i = (size_t)blockIdx.x * blockDim.x + threadIdx.x;
    if (i >= (size_t)H_DIM * (KPAD / 4)) return;
    int row = (int)(i / (KPAD / 4));
    int k4  = (int)(i % (KPAD / 4));
    int k   = k4 * 4;
    char4 s = make_char4(0, 0, 0, 0);
    if (k < IN_DIM) {
        float4 wv = *(const float4*)(W1 + (size_t)row * IN_DIM + k);
        float v[4] = {wv.x, wv.y, wv.z, wv.w};
        signed char sc[4];
        #pragma unroll
        for (int j = 0; j < 4; j++)
            sc[j] = (signed char)((v[j] > 0.f) ? 1 : ((v[j] < 0.f) ? -1 : 0));
        s = make_char4(sc[0], sc[1], sc[2], sc[3]);
    }
    *(char4*)(g_Bs + (size_t)row * KPAD + k) = s;
}

__global__ void k_prep_w2(const float* __restrict__ W2) {
    int idx = blockIdx.x * blockDim.x + threadIdx.x;
    if (idx >= OUT_DIM * 128) return;
    int o = idx / 128, w = idx % 128;
    unsigned bits = 0;
    for (int j = 0; j < 32; j++)
        if (W2[(size_t)o * H_DIM + w * 32 + j] > 0.f) bits |= (1u << j);
    g_w2b[idx] = bits;
}

// ---------------- GEMM1: 512 threads, register-pipelined fragments ----------------
__global__ void __launch_bounds__(512, 1) k_gemm1() {
    extern __shared__ __align__(128) char smem[];
    const uint32_t sb = smem_u32(smem);
    const int tid = threadIdx.x, lane = tid & 31, wid = tid >> 5;
    const int wm = wid & 3, wn = wid >> 2;       // 4 x 4 warp grid
    const int mbase = blockIdx.y * MT;
    const int nbase = blockIdx.x * NT;

    // cp.async granule plan: 1280 granules/stage; threads get granules tid, tid+512, (tid<256: tid+1024)
    const int ng = (tid < 256) ? 3 : 2;
    const int8_t* gsrc[3];
    uint32_t sdst[3];
    #pragma unroll
    for (int i = 0; i < 3; i++) {
        int g = tid + i * 512;
        if (g >= 1280) g = 0;   // dummy (unused when i >= ng)
        if (g < 768) {
            int limb = g >> 8, rem = g & 255, row = rem >> 2, c = rem & 3;
            gsrc[i] = g_Aq + ((size_t)(mbase + row) * 3 + limb) * KPAD + c * 16;
            sdst[i] = limb * A_LIMB_B + row * A_ROWB + c * 16;
        } else {
            int gb = g - 768, row = gb >> 2, c = gb & 3;
            gsrc[i] = g_Bs + (size_t)(nbase + row) * KPAD + c * 16;
            sdst[i] = STAGE_A_B + row * A_ROWB + c * 16;
        }
    }

    // ldmatrix lane offsets
    const int mi = lane >> 3, r8 = lane & 7;
    const uint32_t aLane = (uint32_t)(((mi & 1) * 8 + r8) * A_ROWB + (mi >> 1) * 16);
    const uint32_t bLane = (uint32_t)(r8 * A_ROWB + (mi & 1) * 16 + (mi >> 1) * 32);
    const uint32_t aWarp = (uint32_t)(wm * 16 * A_ROWB) + aLane;
    const uint32_t bWarp = (uint32_t)(wn * 32 * A_ROWB) + bLane;

    int d[3][4][4];
    #pragma unroll
    for (int l = 0; l < 3; l++)
        #pragma unroll
        for (int nb = 0; nb < 4; nb++)
            #pragma unroll
            for (int i = 0; i < 4; i++) d[l][nb][i] = 0;

    // prologue: cp.async stages 0..2
    #pragma unroll
    for (int s = 0; s < STAGES - 1; s++) {
        #pragma unroll
        for (int i = 0; i < 3; i++)
            if (i < ng) cp_async16(sb + s * STAGE_BYTES + sdst[i], gsrc[i] + s * 64);
        cp_commit();
    }

    uint32_t bfr[2][4][4];              // double-buffered B fragments
    uint32_t afr[3][2][4];              // A fragments (single-buffered, reloaded per-limb)

    // wait for stage 0, load chunk-0 fragments
    asm volatile("cp.async.wait_group 2;" ::: "memory");
    __syncthreads();
    {
        const uint32_t sA = sb, sB = sb + STAGE_A_B;
        #pragma unroll
        for (int nb = 0; nb < 4; nb++)
            ldsm4(sB + bWarp + (uint32_t)(nb * 8 * A_ROWB), bfr[0][nb]);
        #pragma unroll
        for (int l = 0; l < 3; l++)
            #pragma unroll
            for (int ks = 0; ks < 2; ks++)
                ldsm4(sA + l * A_LIMB_B + aWarp + (uint32_t)(ks * 32), afr[l][ks]);
    }

    for (int kc = 0; kc < NCHUNK; kc++) {
        const int cur = kc & 1, nxt = cur ^ 1;

        // prefetch smem stage kc+3
        if (kc + 3 < NCHUNK) {
            int s = (kc + 3) % STAGES;
            #pragma unroll
            for (int i = 0; i < 3; i++)
                if (i < ng) cp_async16(sb + s * STAGE_BYTES + sdst[i], gsrc[i] + (kc + 3) * 64);
            cp_commit();
        }

        const uint32_t sAn = sb + ((kc + 1) % STAGES) * STAGE_BYTES;
        const uint32_t sBn = sAn + STAGE_A_B;

        if (kc + 1 < NCHUNK) {
            // make stage kc+1 visible
            if (kc <= 9)       asm volatile("cp.async.wait_group 2;" ::: "memory");
            else if (kc == 10) asm volatile("cp.async.wait_group 1;" ::: "memory");
            else               asm volatile("cp.async.wait_group 0;" ::: "memory");
            __syncthreads();
            // B fragments for chunk kc+1 (into alternate buffer; not needed until next iter)
            #pragma unroll
            for (int nb = 0; nb < 4; nb++)
                ldsm4(sBn + bWarp + (uint32_t)(nb * 8 * A_ROWB), bfr[nxt][nb]);
        }

        // MMAs for chunk kc (fragments already in registers); reload A per-limb behind them
        #pragma unroll
        for (int l = 0; l < 3; l++) {
            #pragma unroll
            for (int ks = 0; ks < 2; ks++)
                #pragma unroll
                for (int nb = 0; nb < 4; nb++)
                    imma(d[l][nb], afr[l][ks], &bfr[cur][nb][ks * 2]);
            if (kc + 1 < NCHUNK) {
                #pragma unroll
                for (int ks = 0; ks < 2; ks++)
                    ldsm4(sAn + l * A_LIMB_B + aWarp + (uint32_t)(ks * 32), afr[l][ks]);
            }
        }
    }

    // ---- epilogue: h = (65536*S2 + 256*S1 + S0) * 2^-20 + fused column stats ----
    float s_loc[4][2], q_loc[4][2];
    #pragma unroll
    for (int nb = 0; nb < 4; nb++) { s_loc[nb][0] = s_loc[nb][1] = 0.f; q_loc[nb][0] = q_loc[nb][1] = 0.f; }

    {
        int row0 = mbase + wm * 16 + (lane >> 2);
        #pragma unroll
        for (int nb = 0; nb < 4; nb++) {
            int col = nbase + wn * 32 + nb * 8 + (lane & 3) * 2;
            float f[4];
            #pragma unroll
            for (int i = 0; i < 4; i++)
                f[i] = fmaf((float)d[2][nb][i], 65536.f,
                            fmaf((float)d[1][nb][i], 256.f,
                                 (float)d[0][nb][i])) * (1.f / 1048576.f);
            *(float2*)(g_h + (size_t)row0 * H_DIM + col)       = make_float2(f[0], f[1]);
            *(float2*)(g_h + (size_t)(row0 + 8) * H_DIM + col) = make_float2(f[2], f[3]);
            s_loc[nb][0] += f[0] + f[2];            q_loc[nb][0] += f[0] * f[0] + f[2] * f[2];
            s_loc[nb][1] += f[1] + f[3];            q_loc[nb][1] += f[1] * f[1] + f[3] * f[3];
        }
    }
    #pragma unroll
    for (int nb = 0; nb < 4; nb++)
        #pragma unroll
        for (int p = 0; p < 2; p++) {
            #pragma unroll
            for (int off = 4; off <= 16; off <<= 1) {
                s_loc[nb][p] += __shfl_xor_sync(0xFFFFFFFFu, s_loc[nb][p], off);
                q_loc[nb][p] += __shfl_xor_sync(0xFFFFFFFFu, q_loc[nb][p], off);
            }
        }
    __syncthreads();
    float* sm_s = (float*)smem;          // [4][128]
    float* sm_q = sm_s + 512;            // [4][128]
    if (lane < 4) {
        #pragma unroll
        for (int nb = 0; nb < 4; nb++)
            #pragma unroll
            for (int p = 0; p < 2; p++) {
                int idx = wn * 32 + nb * 8 + lane * 2 + p;
                sm_s[wm * 128 + idx] = s_loc[nb][p];
                sm_q[wm * 128 + idx] = q_loc[nb][p];
            }
    }
    __syncthreads();
    if (tid < 128) {
        float s = ((sm_s[tid] + sm_s[128 + tid]) + sm_s[256 + tid]) + sm_s[384 + tid];
        float q = ((sm_q[tid] + sm_q[128 + tid]) + sm_q[256 + tid]) + sm_q[384 + tid];
        size_t gidx = (size_t)blockIdx.y * H_DIM + nbase + tid;
        g_psum[gidx] = s;
        g_psq [gidx] = q;
    }
}

// ---------------- stats finalize: reduce 256 mtile partials ----------------
__global__ void __launch_bounds__(256) k_stats_fin(const float* __restrict__ gamma,
                                                   const float* __restrict__ beta) {
    int j = blockIdx.x * 256 + threadIdx.x;
    float s = 0.f, q = 0.f;
    for (int p = 0; p < MTILES; p++) {
        s += g_psum[(size_t)p * H_DIM + j];
        q += g_psq [(size_t)p * H_DIM + j];
    }
    float mean = s * (1.f / B_DIM);
    float var  = q * (1.f / B_DIM) - mean * mean;
    float a = gamma[j] * rsqrtf(var + 1e-5f);
    float t; unsigned neg;
    if (a != 0.f) { t = mean - beta[j] / a; neg = (a < 0.f) ? 1u : 0u; }
    else { t = (beta[j] > 0.f) ? -__int_as_float(0x7f800000) : __int_as_float(0x7f800000); neg = 0u; }
    g_thr[j] = t;
    unsigned word = __ballot_sync(0xFFFFFFFFu, neg);
    if ((threadIdx.x & 31) == 0) g_negw[j >> 5] = word;
}

// ---------------- fused sign / XOR-popcount GEMM2 / log-softmax ----------------
__global__ void __launch_bounds__(128) k_final(float* __restrict__ out) {
    int row = blockIdx.x;
    __shared__ unsigned hw[128];
    __shared__ int wsum[4][OUT_DIM];
    int tid = threadIdx.x, lane = tid & 31, w = tid >> 5;
    const float* hr = g_h + (size_t)row * H_DIM;
    for (int c = w; c < 128; c += 4) {
        int col = c * 32 + lane;
        unsigned bit = (hr[col] > g_thr[col]) ? 1u : 0u;
        unsigned word = __ballot_sync(0xFFFFFFFFu, bit);
        if (lane == 0) hw[c] = word ^ g_negw[c];
    }
    __syncthreads();
    unsigned mw = hw[tid];
    #pragma unroll
    for (int o = 0; o < OUT_DIM; o++) {
        int v = __popc(mw ^ g_w2b[o * 128 + tid]);
        v = (int)__reduce_add_sync(0xFFFFFFFFu, (unsigned)v);
        if (lane == 0) wsum[w][o] = v;
    }
    __syncthreads();
    if (tid == 0) {
        float lg[OUT_DIM], mx = -3.4e38f;
        #pragma unroll
        for (int o = 0; o < OUT_DIM; o++) {
            int mis = wsum[0][o] + wsum[1][o] + wsum[2][o] + wsum[3][o];
            lg[o] = (float)(H_DIM - 2 * mis);
            mx = fmaxf(mx, lg[o]);
        }
        float se = 0.f;
        #pragma unroll
        for (int o = 0; o < OUT_DIM; o++) se += expf(lg[o] - mx);
        float lse = mx + logf(se);
        #pragma unroll
        for (int o = 0; o < OUT_DIM; o++) out[(size_t)row * OUT_DIM + o] = lg[o] - lse;
    }
}

// ---------------- launch ----------------
extern "C" void kernel_launch(void* const* d_in, const int* in_sizes, int n_in,
                              void* d_out, int out_size) {
    (void)in_sizes; (void)n_in; (void)out_size;
    const float* x     = (const float*)d_in[0];
    const float* W1    = (const float*)d_in[1];
    const float* gamma = (const float*)d_in[2];
    const float* beta  = (const float*)d_in[3];
    const float* W2    = (const float*)d_in[4];

    cudaFuncSetAttribute(k_gemm1, cudaFuncAttributeMaxDynamicSharedMemorySize, SMEM_TOTAL);

    {
        size_t n = (size_t)B_DIM * (KPAD / 4);
        k_prep_a<<<(unsigned)((n + 255) / 256), 256>>>(x);
    }
    {
        size_t n = (size_t)H_DIM * (KPAD / 4);
        k_prep_w<<<(unsigned)((n + 255) / 256), 256>>>(W1);
    }
    k_prep_w2<<<10, 128>>>(W2);

    k_gemm1<<<dim3(H_DIM / NT, B_DIM / MT), 512, SMEM_TOTAL>>>();

    k_stats_fin<<<H_DIM / 256, 256>>>(gamma, beta);

    k_final<<<B_DIM, 128>>>((float*)d_out);
}